// round 11
// baseline (speedup 1.0000x reference)
#include <cuda_runtime.h>
#include <cuda_bf16.h>
#include <cstdint>

// ---------------------------------------------------------------------------
// weighted_loss: fused per-row loss + global mean, SINGLE kernel.
//   pred [B,3] f32, true [B,3] f32, ot [B] i32  ->  scalar f32
// 112 MiB streamed once; last-arriving block finishes the reduction.
// ---------------------------------------------------------------------------

static constexpr int MAX_BLOCKS = 8192;

__device__ double g_part[MAX_BLOCKS];     // per-block partials (rewritten every launch)
__device__ unsigned int g_count = 0;      // reset to 0 by the last block each launch

__constant__ float c_pow11[6] = {1.0f, 1.1f, 1.21f, 1.331f, 1.4641f, 1.61051f};
__constant__ float c_ot_scale[5] = {0.8f, 0.9f, 1.0f, 1.1f, 1.2f};

__device__ __forceinline__ int ais5(float x, float t0, float t1, float t2,
                                    float t3, float t4) {
    return (int)(x >= t0) + (int)(x >= t1) + (int)(x >= t2) +
           (int)(x >= t3) + (int)(x >= t4);
}

// 1 + piecewise_linear(t, p, params, mid=1). k = ln2/d, inv_a=1/a, inv_cb=1/(c-b)
__device__ __forceinline__ float w_mid(float t, float p, float a, float b,
                                       float c, float d, float k,
                                       float inv_a, float inv_cb) {
    float we = __expf(-k * (t - d)) - 1.0f;   // inf for small t, selected away
    float w;
    if (t > d)         w = we;
    else if (t >= c)   w = 0.0f;
    else if (t > b)    w = 1.0f - inv_cb * (t - b);
    else if (t >= a)   w = 1.0f;
    else if (t >= 0.f) w = inv_a * t;
    else               w = 0.0f;
    if (p < 0.0f) w += 1.0f;
    return 1.0f + w;
}

__device__ __forceinline__ float row_loss(float ph, float th,
                                          float pc, float tc,
                                          float pn, float tn,
                                          int ot) {
    // HIC (head): a=80 b=1500 c=1750 d=2000
    int ap = ais5(ph, 150.f, 500.f, 1000.f, 1800.f, 2600.f);
    int at = ais5(th, 150.f, 500.f, 1000.f, 1800.f, 2600.f);
    float wcls = c_pow11[abs(ap - at)];
    float wm = w_mid(th, ph, 80.f, 1500.f, 1750.f, 2000.f,
                     3.46573590e-4f, 0.0125f, 0.004f);
    float loss = fabsf(ph - th) * wcls * wm;

    // Dmax (chest): thresholds scaled per occupant type
    float s = c_ot_scale[ot];
    ap = ais5(pc, 22.f * s, 35.f * s, 45.f * s, 55.f * s, 65.f * s);
    at = ais5(tc, 22.f * s, 35.f * s, 45.f * s, 55.f * s, 65.f * s);
    wcls = c_pow11[abs(ap - at)];
    wm = w_mid(tc, pc, 10.f, 75.f, 85.f, 100.f,
               6.93147181e-3f, 0.1f, 0.1f);
    loss += fabsf(pc - tc) * wcls * wm;

    // Nij (neck)
    ap = ais5(pn, 0.2f, 0.5f, 1.0f, 1.5f, 2.0f);
    at = ais5(tn, 0.2f, 0.5f, 1.0f, 1.5f, 2.0f);
    wcls = c_pow11[abs(ap - at)];
    wm = w_mid(tn, pn, 0.15f, 1.5f, 1.7f, 1.9f,
               0.364814311f, 6.66666651f, 5.0f);
    loss += fabsf(pn - tn) * wcls * wm;

    return loss;
}

__device__ __forceinline__ float do4(const float4* p4, const float4* t4,
                                     const int4 o4) {
    float4 pa = p4[0], pb = p4[1], pc4 = p4[2];
    float4 ta = t4[0], tb = t4[1], tc4 = t4[2];
    float acc;
    acc  = row_loss(pa.x, ta.x, pa.y, ta.y, pa.z, ta.z, o4.x);
    acc += row_loss(pa.w, ta.w, pb.x, tb.x, pb.y, tb.y, o4.y);
    acc += row_loss(pb.z, tb.z, pb.w, tb.w, pc4.x, tc4.x, o4.z);
    acc += row_loss(pc4.y, tc4.y, pc4.z, tc4.z, pc4.w, tc4.w, o4.w);
    return acc;
}

__global__ __launch_bounds__(256)
void loss_kernel(const float* __restrict__ pred,
                 const float* __restrict__ tru,
                 const int*   __restrict__ ot,
                 float* __restrict__ out,
                 int B, double inv_b) {
    const int tid = blockIdx.x * blockDim.x + threadIdx.x;
    const int r0 = tid * 8;                 // 8 rows per thread

    float acc = 0.0f;
    if (r0 + 7 < B) {
        // 8 rows = 24 floats = 6 float4 per array; ot: 2 int4. All issued up
        // front -> MLP ~14 per thread.
        const float4* p4 = reinterpret_cast<const float4*>(pred + (size_t)r0 * 3);
        const float4* t4 = reinterpret_cast<const float4*>(tru  + (size_t)r0 * 3);
        const int4*   o4 = reinterpret_cast<const int4*>(ot + r0);
        int4 oA = o4[0], oB = o4[1];
        acc  = do4(p4,     t4,     oA);
        acc += do4(p4 + 3, t4 + 3, oB);
    } else {
        for (int r = r0; r < B; ++r) {
            acc += row_loss(pred[(size_t)r * 3 + 0], tru[(size_t)r * 3 + 0],
                            pred[(size_t)r * 3 + 1], tru[(size_t)r * 3 + 1],
                            pred[(size_t)r * 3 + 2], tru[(size_t)r * 3 + 2],
                            ot[r]);
        }
    }

    // ---- block reduction (float within block) ----
    #pragma unroll
    for (int off = 16; off > 0; off >>= 1)
        acc += __shfl_xor_sync(0xffffffffu, acc, off);

    __shared__ float  s_part[8];
    __shared__ bool   s_last;
    const int lane = threadIdx.x & 31;
    const int warp = threadIdx.x >> 5;
    if (lane == 0) s_part[warp] = acc;
    __syncthreads();

    if (threadIdx.x == 0) {
        float v = 0.0f;
        #pragma unroll
        for (int w = 0; w < 8; ++w) v += s_part[w];
        g_part[blockIdx.x] = (double)v;
        __threadfence();
        unsigned int c = atomicAdd(&g_count, 1u);
        s_last = (c == gridDim.x - 1);
    }
    __syncthreads();

    // ---- last-arriving block finishes: reduce partials, write scalar ----
    if (s_last) {
        double v = 0.0;
        for (int i = threadIdx.x; i < (int)gridDim.x; i += blockDim.x)
            v += g_part[i];
        #pragma unroll
        for (int off = 16; off > 0; off >>= 1)
            v += __shfl_xor_sync(0xffffffffu, v, off);

        __shared__ double s_d[8];
        if (lane == 0) s_d[warp] = v;
        __syncthreads();
        if (threadIdx.x == 0) {
            double t = 0.0;
            #pragma unroll
            for (int w = 0; w < 8; ++w) t += s_d[w];
            out[0] = (float)(t * inv_b);
            g_count = 0;                    // reset for next graph replay
        }
    }
}

extern "C" void kernel_launch(void* const* d_in, const int* in_sizes, int n_in,
                              void* d_out, int out_size) {
    const float* pred = (const float*)d_in[0];
    const float* tru  = (const float*)d_in[1];
    const int*   ot   = (const int*)d_in[2];
    float* out = (float*)d_out;

    const int B = in_sizes[2];
    const int threads = 256;
    const int rows_per_thread = 8;
    const int total_threads = (B + rows_per_thread - 1) / rows_per_thread;
    int blocks = (total_threads + threads - 1) / threads;
    if (blocks > MAX_BLOCKS) blocks = MAX_BLOCKS;   // B=4.2M -> 2048, safe

    loss_kernel<<<blocks, threads>>>(pred, tru, ot, out, B, 1.0 / (double)B);
}

// round 16
// speedup vs baseline: 1.1200x; 1.1200x over previous
#include <cuda_runtime.h>
#include <cuda_bf16.h>
#include <cstdint>

// ---------------------------------------------------------------------------
// weighted_loss: fused per-row loss + global mean, SINGLE kernel.
//   pred [B,3] f32, true [B,3] f32, ot [B] i32  ->  scalar f32
// Issue-bound previously (~300 SASS inst/row). This version: branchless
// product-form w_cls, min/max-identity w_mid, ex2-based exp tail.
// ---------------------------------------------------------------------------

static constexpr int MAX_BLOCKS = 8192;

__device__ double g_part[MAX_BLOCKS];   // per-block partials (rewritten every launch)
__device__ unsigned int g_count = 0;    // reset by last block each launch

__device__ __forceinline__ float ex2_approx(float x) {
    float r;
    asm("ex2.approx.f32 %0, %1;" : "=f"(r) : "f"(x));
    return r;
}
__device__ __forceinline__ float rcp_approx(float x) {
    float r;
    asm("rcp.approx.f32 %0, %1;" : "=f"(r) : "f"(x));
    return r;
}

// w_cls = 1.1^{#thresholds where (p>=u) != (t>=u)}  (product form, no table)
__device__ __forceinline__ float wcls5(float p, float t,
                                       float u0, float u1, float u2,
                                       float u3, float u4) {
    float f = ((p >= u0) != (t >= u0)) ? 1.1f : 1.0f;
    f *= ((p >= u1) != (t >= u1)) ? 1.1f : 1.0f;
    f *= ((p >= u2) != (t >= u2)) ? 1.1f : 1.0f;
    f *= ((p >= u3) != (t >= u3)) ? 1.1f : 1.0f;
    f *= ((p >= u4) != (t >= u4)) ? 1.1f : 1.0f;
    return f;
}

// w_mid = 1 + piecewise_linear(t, p, params, mid=1), branchless.
// For t <= d:  w = clamp(min(t*inv_a, (c-t)*inv_cb), 0, 1)
//   (covers t<0 -> 0, [0,a) ramp-up, [a,b] -> 1, (b,c) ramp-down, [c,d] -> 0)
// For t  > d:  w = exp(-k(t-d)) - 1 = 2^(1 - t/d) - 1   (since k = ln2/d)
// Plus +1 if p < 0; final +1 for the "1 +" term.
__device__ __forceinline__ float wmid(float t, float p,
                                      float inv_a, float inv_cb, float c_cb,
                                      float d, float inv_d) {
    float m = fminf(t * inv_a, fmaf(-inv_cb, t, c_cb));
    m = fmaxf(fminf(m, 1.0f), 0.0f);
    float we = ex2_approx(fmaf(-inv_d, t, 1.0f)) - 1.0f;
    float w = (t > d) ? we : m;
    return w + ((p < 0.0f) ? 2.0f : 1.0f);
}

__device__ __forceinline__ float row_loss(float ph, float th,
                                          float pc, float tc,
                                          float pn, float tn,
                                          int ot) {
    // ---- HIC (head): a=80 b=1500 c=1750 d=2000, thr 150/500/1000/1800/2600
    float wc = wcls5(ph, th, 150.f, 500.f, 1000.f, 1800.f, 2600.f);
    float wm = wmid(th, ph, 0.0125f, 0.004f, 7.0f, 2000.f, 5.0e-4f);
    float acc = fabsf(ph - th) * wc * wm;

    // ---- Dmax (chest): a=10 b=75 c=85 d=100, thr {22,35,45,55,65}*s[ot]
    // Compare p/s, t/s against fixed thresholds (rcp.approx: ~3ulp window,
    // negligible over a 4.2M mean).
    float s  = fmaf(0.1f, (float)ot, 0.8f);
    float is = rcp_approx(s);
    wc = wcls5(pc * is, tc * is, 22.f, 35.f, 45.f, 55.f, 65.f);
    wm = wmid(tc, pc, 0.1f, 0.1f, 8.5f, 100.f, 0.01f);
    acc += fabsf(pc - tc) * wc * wm;

    // ---- Nij (neck): a=0.15 b=1.5 c=1.7 d=1.9, thr 0.2/0.5/1/1.5/2
    wc = wcls5(pn, tn, 0.2f, 0.5f, 1.0f, 1.5f, 2.0f);
    wm = wmid(tn, pn, 6.66666651f, 5.0f, 8.5f, 1.9f, 0.526315808f);
    acc += fabsf(pn - tn) * wc * wm;

    return acc;
}

__device__ __forceinline__ float do4(const float4* p4, const float4* t4,
                                     const int4 o4) {
    float4 pa = p4[0], pb = p4[1], pc4 = p4[2];
    float4 ta = t4[0], tb = t4[1], tc4 = t4[2];
    float acc;
    acc  = row_loss(pa.x, ta.x, pa.y, ta.y, pa.z, ta.z, o4.x);
    acc += row_loss(pa.w, ta.w, pb.x, tb.x, pb.y, tb.y, o4.y);
    acc += row_loss(pb.z, tb.z, pb.w, tb.w, pc4.x, tc4.x, o4.z);
    acc += row_loss(pc4.y, tc4.y, pc4.z, tc4.z, pc4.w, tc4.w, o4.w);
    return acc;
}

__global__ __launch_bounds__(256)
void loss_kernel(const float* __restrict__ pred,
                 const float* __restrict__ tru,
                 const int*   __restrict__ ot,
                 float* __restrict__ out,
                 int B, double inv_b) {
    const int tid = blockIdx.x * blockDim.x + threadIdx.x;
    const int r0 = tid * 4;                  // 4 rows per thread (R1 shape)

    float acc = 0.0f;
    if (r0 + 3 < B) {
        // 4 rows = 12 floats = 3 x float4 per array (48B groups, 16B aligned)
        const float4* p4 = reinterpret_cast<const float4*>(pred + (size_t)r0 * 3);
        const float4* t4 = reinterpret_cast<const float4*>(tru  + (size_t)r0 * 3);
        int4 o4 = *reinterpret_cast<const int4*>(ot + r0);
        acc = do4(p4, t4, o4);
    } else {
        for (int r = r0; r < B; ++r) {
            acc += row_loss(pred[(size_t)r * 3 + 0], tru[(size_t)r * 3 + 0],
                            pred[(size_t)r * 3 + 1], tru[(size_t)r * 3 + 1],
                            pred[(size_t)r * 3 + 2], tru[(size_t)r * 3 + 2],
                            ot[r]);
        }
    }

    // ---- block reduction ----
    #pragma unroll
    for (int off = 16; off > 0; off >>= 1)
        acc += __shfl_xor_sync(0xffffffffu, acc, off);

    __shared__ float s_part[8];
    __shared__ bool  s_last;
    const int lane = threadIdx.x & 31;
    const int warp = threadIdx.x >> 5;
    if (lane == 0) s_part[warp] = acc;
    __syncthreads();

    if (threadIdx.x == 0) {
        float v = 0.0f;
        #pragma unroll
        for (int w = 0; w < 8; ++w) v += s_part[w];
        g_part[blockIdx.x] = (double)v;
        __threadfence();
        unsigned int c = atomicAdd(&g_count, 1u);
        s_last = (c == gridDim.x - 1);
    }
    __syncthreads();

    // ---- last block finishes: reduce partials, write scalar, reset counter ----
    if (s_last) {
        double v = 0.0;
        for (int i = threadIdx.x; i < (int)gridDim.x; i += blockDim.x)
            v += g_part[i];
        #pragma unroll
        for (int off = 16; off > 0; off >>= 1)
            v += __shfl_xor_sync(0xffffffffu, v, off);

        __shared__ double s_d[8];
        if (lane == 0) s_d[warp] = v;
        __syncthreads();
        if (threadIdx.x == 0) {
            double t = 0.0;
            #pragma unroll
            for (int w = 0; w < 8; ++w) t += s_d[w];
            out[0] = (float)(t * inv_b);
            g_count = 0;   // deterministic reset for next graph replay
        }
    }
}

extern "C" void kernel_launch(void* const* d_in, const int* in_sizes, int n_in,
                              void* d_out, int out_size) {
    const float* pred = (const float*)d_in[0];
    const float* tru  = (const float*)d_in[1];
    const int*   ot   = (const int*)d_in[2];
    float* out = (float*)d_out;

    const int B = in_sizes[2];
    const int threads = 256;
    const int rows_per_thread = 4;
    const int total_threads = (B + rows_per_thread - 1) / rows_per_thread;
    int blocks = (total_threads + threads - 1) / threads;
    if (blocks > MAX_BLOCKS) blocks = MAX_BLOCKS;  // B=4.2M -> 4096, safe

    loss_kernel<<<blocks, threads>>>(pred, tru, ot, out, B, 1.0 / (double)B);
}

// round 17
// speedup vs baseline: 1.1593x; 1.0351x over previous
#include <cuda_runtime.h>
#include <cuda_bf16.h>
#include <cstdint>

// ---------------------------------------------------------------------------
// weighted_loss: fused per-row loss + global mean, SINGLE kernel.
//   pred [B,3] f32, true [B,3] f32, ot [B] i32  ->  scalar f32
// R16 was issue/latency-bound (~170 inst/row). This round:
//   - wmid select removed via  w = clamp_ramp + min(exp_tail, 0)  identity
//   - wcls via predicated FMUL (no FSEL)
// ---------------------------------------------------------------------------

static constexpr int MAX_BLOCKS = 8192;

__device__ double g_part[MAX_BLOCKS];   // per-block partials (rewritten every launch)
__device__ unsigned int g_count = 0;    // reset by last block each launch

__device__ __forceinline__ float ex2_approx(float x) {
    float r;
    asm("ex2.approx.f32 %0, %1;" : "=f"(r) : "f"(x));
    return r;
}
__device__ __forceinline__ float rcp_approx(float x) {
    float r;
    asm("rcp.approx.f32 %0, %1;" : "=f"(r) : "f"(x));
    return r;
}

// w_cls = 1.1^{#thresholds where (p>=u) != (t>=u)}
// Written as predicated multiplies: FSETP.AND + FSETP.XOR + @P FMUL per thr.
__device__ __forceinline__ float wcls5(float p, float t,
                                       float u0, float u1, float u2,
                                       float u3, float u4) {
    float f = 1.0f;
    if ((p >= u0) != (t >= u0)) f *= 1.1f;
    if ((p >= u1) != (t >= u1)) f *= 1.1f;
    if ((p >= u2) != (t >= u2)) f *= 1.1f;
    if ((p >= u3) != (t >= u3)) f *= 1.1f;
    if ((p >= u4) != (t >= u4)) f *= 1.1f;
    return f;
}

// w_mid = 1 + piecewise_linear(t, p, params, mid=1), fully select-free:
//   ramp m = clamp(min(t*inv_a, (c-t)*inv_cb), 0, 1)   -- exact for t <= d
//   tail we = 2^(1 - t/d) - 1                          -- exact for t > d
// Identity: for t<=d we>=0 and m is the answer; for t>d m==0 and we<0.
//   => w = m + min(we, 0)
// (+1 base, +1 more if p < 0)
__device__ __forceinline__ float wmid(float t, float p,
                                      float inv_a, float inv_cb, float c_cb,
                                      float inv_d) {
    float m = fminf(t * inv_a, fmaf(-inv_cb, t, c_cb));
    m = fmaxf(fminf(m, 1.0f), 0.0f);
    float we = ex2_approx(fmaf(-inv_d, t, 1.0f)) - 1.0f;
    float w = m + fminf(we, 0.0f);
    return w + ((p < 0.0f) ? 2.0f : 1.0f);
}

__device__ __forceinline__ float row_loss(float ph, float th,
                                          float pc, float tc,
                                          float pn, float tn,
                                          int ot) {
    // ---- HIC (head): a=80 b=1500 c=1750 d=2000, thr 150/500/1000/1800/2600
    float wc = wcls5(ph, th, 150.f, 500.f, 1000.f, 1800.f, 2600.f);
    float wm = wmid(th, ph, 0.0125f, 0.004f, 7.0f, 5.0e-4f);
    float acc = fabsf(ph - th) * wc * wm;

    // ---- Dmax (chest): a=10 b=75 c=85 d=100, thr {22,35,45,55,65}*s[ot]
    // Normalize by rcp(s) so thresholds stay immediates (no LDC in hot loop:
    // LDC rt-floor 8/SMSP would dominate at 1/row).
    float s  = fmaf(0.1f, (float)ot, 0.8f);
    float is = rcp_approx(s);
    wc = wcls5(pc * is, tc * is, 22.f, 35.f, 45.f, 55.f, 65.f);
    wm = wmid(tc, pc, 0.1f, 0.1f, 8.5f, 0.01f);
    acc += fabsf(pc - tc) * wc * wm;

    // ---- Nij (neck): a=0.15 b=1.5 c=1.7 d=1.9, thr 0.2/0.5/1/1.5/2
    wc = wcls5(pn, tn, 0.2f, 0.5f, 1.0f, 1.5f, 2.0f);
    wm = wmid(tn, pn, 6.66666651f, 5.0f, 8.5f, 0.526315808f);
    acc += fabsf(pn - tn) * wc * wm;

    return acc;
}

__device__ __forceinline__ float do4(const float4* p4, const float4* t4,
                                     const int4 o4) {
    float4 pa = p4[0], pb = p4[1], pc4 = p4[2];
    float4 ta = t4[0], tb = t4[1], tc4 = t4[2];
    float acc;
    acc  = row_loss(pa.x, ta.x, pa.y, ta.y, pa.z, ta.z, o4.x);
    acc += row_loss(pa.w, ta.w, pb.x, tb.x, pb.y, tb.y, o4.y);
    acc += row_loss(pb.z, tb.z, pb.w, tb.w, pc4.x, tc4.x, o4.z);
    acc += row_loss(pc4.y, tc4.y, pc4.z, tc4.z, pc4.w, tc4.w, o4.w);
    return acc;
}

__global__ __launch_bounds__(256)
void loss_kernel(const float* __restrict__ pred,
                 const float* __restrict__ tru,
                 const int*   __restrict__ ot,
                 float* __restrict__ out,
                 int B, double inv_b) {
    const int tid = blockIdx.x * blockDim.x + threadIdx.x;
    const int r0 = tid * 4;                  // 4 rows per thread

    float acc = 0.0f;
    if (r0 + 3 < B) {
        const float4* p4 = reinterpret_cast<const float4*>(pred + (size_t)r0 * 3);
        const float4* t4 = reinterpret_cast<const float4*>(tru  + (size_t)r0 * 3);
        int4 o4 = *reinterpret_cast<const int4*>(ot + r0);
        acc = do4(p4, t4, o4);
    } else {
        for (int r = r0; r < B; ++r) {
            acc += row_loss(pred[(size_t)r * 3 + 0], tru[(size_t)r * 3 + 0],
                            pred[(size_t)r * 3 + 1], tru[(size_t)r * 3 + 1],
                            pred[(size_t)r * 3 + 2], tru[(size_t)r * 3 + 2],
                            ot[r]);
        }
    }

    // ---- block reduction ----
    #pragma unroll
    for (int off = 16; off > 0; off >>= 1)
        acc += __shfl_xor_sync(0xffffffffu, acc, off);

    __shared__ float s_part[8];
    __shared__ bool  s_last;
    const int lane = threadIdx.x & 31;
    const int warp = threadIdx.x >> 5;
    if (lane == 0) s_part[warp] = acc;
    __syncthreads();

    if (threadIdx.x == 0) {
        float v = 0.0f;
        #pragma unroll
        for (int w = 0; w < 8; ++w) v += s_part[w];
        g_part[blockIdx.x] = (double)v;
        __threadfence();
        unsigned int c = atomicAdd(&g_count, 1u);
        s_last = (c == gridDim.x - 1);
    }
    __syncthreads();

    // ---- last block finishes: reduce partials, write scalar, reset counter ----
    if (s_last) {
        double v = 0.0;
        for (int i = threadIdx.x; i < (int)gridDim.x; i += blockDim.x)
            v += g_part[i];
        #pragma unroll
        for (int off = 16; off > 0; off >>= 1)
            v += __shfl_xor_sync(0xffffffffu, v, off);

        __shared__ double s_d[8];
        if (lane == 0) s_d[warp] = v;
        __syncthreads();
        if (threadIdx.x == 0) {
            double t = 0.0;
            #pragma unroll
            for (int w = 0; w < 8; ++w) t += s_d[w];
            out[0] = (float)(t * inv_b);
            g_count = 0;   // deterministic reset for next graph replay
        }
    }
}

extern "C" void kernel_launch(void* const* d_in, const int* in_sizes, int n_in,
                              void* d_out, int out_size) {
    const float* pred = (const float*)d_in[0];
    const float* tru  = (const float*)d_in[1];
    const int*   ot   = (const int*)d_in[2];
    float* out = (float*)d_out;

    const int B = in_sizes[2];
    const int threads = 256;
    const int rows_per_thread = 4;
    const int total_threads = (B + rows_per_thread - 1) / rows_per_thread;
    int blocks = (total_threads + threads - 1) / threads;
    if (blocks > MAX_BLOCKS) blocks = MAX_BLOCKS;  // B=4.19M -> 4096 exactly

    loss_kernel<<<blocks, threads>>>(pred, tru, ot, out, B, 1.0 / (double)B);
}